// round 6
// baseline (speedup 1.0000x reference)
#include <cuda_runtime.h>
#include <cstdint>
#include <cstddef>

#define S_    128
#define B_    64
#define V_    32000
#define E_    32
#define H_    16
#define ROWS  (S_ * B_)        // 8192
#define VCHUNK 3200
#define NCHUNK 10
#define NPART  (NCHUNK * 4)    // per-warp partials

typedef unsigned long long ull;

// ---------------- device scratch ----------------
__device__ float g_xw[ROWS * H_];        // X @ Wx
__device__ float g_h[ROWS * H_];         // hidden states (plain fp32)
__device__ float g_part[NPART * ROWS];   // per-(chunk,warp) partial expsums
__device__ float g_lse[ROWS];

// ---------------- f32x2 helpers ----------------
__device__ __forceinline__ ull ffma2(ull a, ull b, ull c) {
    ull d; asm("fma.rn.f32x2 %0, %1, %2, %3;" : "=l"(d) : "l"(a), "l"(b), "l"(c));
    return d;
}
__device__ __forceinline__ ull fadd2(ull a, ull b) {
    ull d; asm("add.rn.f32x2 %0, %1, %2;" : "=l"(d) : "l"(a), "l"(b));
    return d;
}
__device__ __forceinline__ ull pack2(float x, float y) {
    ull r; asm("mov.b64 %0, {%1, %2};" : "=l"(r) : "f"(x), "f"(y));
    return r;
}
__device__ __forceinline__ void unpack2(ull v, float& x, float& y) {
    asm("mov.b64 {%0, %1}, %2;" : "=f"(x), "=f"(y) : "l"(v));
}

// ---------------- k1: xw = lookup[idx] @ Wx ----------------
__global__ void k_embed_xw(const int* __restrict__ idx,
                           const float* __restrict__ lookup,
                           const float* __restrict__ wx) {
    __shared__ float sWx[E_ * H_];
    for (int i = threadIdx.x; i < E_ * H_; i += blockDim.x) sWx[i] = wx[i];
    __syncthreads();

    int r = blockIdx.x * blockDim.x + threadIdx.x;
    int id = idx[r];
    float x[E_];
    const float4* lp = reinterpret_cast<const float4*>(lookup + (size_t)id * E_);
    #pragma unroll
    for (int i = 0; i < E_ / 4; i++) {
        float4 t = lp[i];
        x[4*i] = t.x; x[4*i+1] = t.y; x[4*i+2] = t.z; x[4*i+3] = t.w;
    }
    #pragma unroll
    for (int h = 0; h < H_; h++) {
        float a = 0.f;
        #pragma unroll
        for (int e = 0; e < E_; e++) a += x[e] * sWx[e * H_ + h];
        g_xw[r * H_ + h] = a;
    }
}

// ---------------- k2: sequential recurrence (single CTA, prefetched) ----
__global__ void k_rnn(const float* __restrict__ wh, const float* __restrict__ h0) {
    __shared__ float sWh[H_ * H_];
    __shared__ float sh[B_ * H_];
    int tid = threadIdx.x;                 // 1024 threads
    if (tid < H_ * H_) sWh[tid] = wh[tid];
    sh[tid] = h0[tid];
    __syncthreads();

    int b = tid >> 4, j = tid & 15;
    float pre = g_xw[tid];
    for (int s = 0; s < S_; s++) {
        float a = pre;
        float nxt = (s < S_ - 1) ? g_xw[(s + 1) * (B_ * H_) + tid] : 0.f;
        #pragma unroll
        for (int k = 0; k < H_; k++) a += sh[b * H_ + k] * sWh[k * H_ + j];
        float hn = tanhf(a);
        __syncthreads();
        sh[tid] = hn;
        g_h[s * (B_ * H_) + tid] = hn;
        pre = nxt;
        __syncthreads();
    }
}

// ---------------- core tile: 16 rows (8 row-pairs), W=4 v per thread ----
// h pairs in shared (broadcast), Wo scalar duplicated via MOV.

__global__ __launch_bounds__(128, 4)
void k_lse_partial(const float* __restrict__ wo) {
    __shared__ __align__(16) ull shp[H_ * 8];   // [k][pair]
    int tid = threadIdx.x, lane = tid & 31, w = tid >> 5;
    int row0 = blockIdx.x * 16;
    {
        int p = tid >> 4, k = tid & 15;
        shp[k * 8 + p] = pack2(g_h[(row0 + 2 * p) * H_ + k],
                               g_h[(row0 + 2 * p + 1) * H_ + k]);
    }
    __syncthreads();

    float s[16];
    #pragma unroll
    for (int r = 0; r < 16; r++) s[r] = 0.f;

    int chunk = blockIdx.y * VCHUNK;

    for (int i = 0;; i++) {
        int voff = i * 512 + w * 128;
        if (voff >= VCHUNK) break;
        const float* wp = wo + chunk + voff + lane * 4;

        ull acc[8][4];
        #pragma unroll
        for (int p = 0; p < 8; p++)
            #pragma unroll
            for (int j = 0; j < 4; j++) acc[p][j] = 0ull;

        #pragma unroll
        for (int k = 0; k < H_; k++) {
            float4 wv = *reinterpret_cast<const float4*>(wp + (size_t)k * V_);
            ull d0 = pack2(wv.x, wv.x), d1 = pack2(wv.y, wv.y);
            ull d2 = pack2(wv.z, wv.z), d3 = pack2(wv.w, wv.w);
            #pragma unroll
            for (int p = 0; p < 8; p += 2) {
                ulonglong2 hp = *reinterpret_cast<const ulonglong2*>(&shp[k * 8 + p]);
                acc[p][0]   = ffma2(hp.x, d0, acc[p][0]);
                acc[p][1]   = ffma2(hp.x, d1, acc[p][1]);
                acc[p][2]   = ffma2(hp.x, d2, acc[p][2]);
                acc[p][3]   = ffma2(hp.x, d3, acc[p][3]);
                acc[p+1][0] = ffma2(hp.y, d0, acc[p+1][0]);
                acc[p+1][1] = ffma2(hp.y, d1, acc[p+1][1]);
                acc[p+1][2] = ffma2(hp.y, d2, acc[p+1][2]);
                acc[p+1][3] = ffma2(hp.y, d3, acc[p+1][3]);
            }
        }
        #pragma unroll
        for (int p = 0; p < 8; p++) {
            #pragma unroll
            for (int j = 0; j < 4; j++) {
                float x, y; unpack2(acc[p][j], x, y);
                s[2 * p]     += __expf(x);
                s[2 * p + 1] += __expf(y);
            }
        }
    }

    #pragma unroll
    for (int r = 0; r < 16; r++) {
        #pragma unroll
        for (int off = 16; off; off >>= 1)
            s[r] += __shfl_xor_sync(0xffffffffu, s[r], off);
    }
    if (lane == 0) {
        float* gp = g_part + (size_t)(blockIdx.y * 4 + w) * ROWS + row0;
        #pragma unroll
        for (int r = 0; r < 16; r++) gp[r] = s[r];
    }
}

// ---------------- k4: lse = log(sum of partials) ----------------------
__global__ void k_lse_final() {
    int r = blockIdx.x * blockDim.x + threadIdx.x;
    float s = 0.f;
    #pragma unroll
    for (int c = 0; c < NPART; c++) s += g_part[(size_t)c * ROWS + r];
    g_lse[r] = logf(s);
}

// ---------------- k5: out = logits - lse ------------------------------
__global__ __launch_bounds__(128, 4)
void k_out(const float* __restrict__ wo, float* __restrict__ out) {
    __shared__ __align__(16) ull shp[H_ * 8];
    int tid = threadIdx.x, lane = tid & 31, w = tid >> 5;
    int row0 = blockIdx.x * 16;
    {
        int p = tid >> 4, k = tid & 15;
        shp[k * 8 + p] = pack2(g_h[(row0 + 2 * p) * H_ + k],
                               g_h[(row0 + 2 * p + 1) * H_ + k]);
    }
    __syncthreads();

    ull nl[8];
    #pragma unroll
    for (int p = 0; p < 8; p++)
        nl[p] = pack2(-g_lse[row0 + 2 * p], -g_lse[row0 + 2 * p + 1]);

    int chunk = blockIdx.y * VCHUNK;

    for (int i = 0;; i++) {
        int voff = i * 512 + w * 128;
        if (voff >= VCHUNK) break;
        int vg = chunk + voff + lane * 4;
        const float* wp = wo + vg;

        ull acc[8][4];
        #pragma unroll
        for (int p = 0; p < 8; p++)
            #pragma unroll
            for (int j = 0; j < 4; j++) acc[p][j] = 0ull;

        #pragma unroll
        for (int k = 0; k < H_; k++) {
            float4 wv = *reinterpret_cast<const float4*>(wp + (size_t)k * V_);
            ull d0 = pack2(wv.x, wv.x), d1 = pack2(wv.y, wv.y);
            ull d2 = pack2(wv.z, wv.z), d3 = pack2(wv.w, wv.w);
            #pragma unroll
            for (int p = 0; p < 8; p += 2) {
                ulonglong2 hp = *reinterpret_cast<const ulonglong2*>(&shp[k * 8 + p]);
                acc[p][0]   = ffma2(hp.x, d0, acc[p][0]);
                acc[p][1]   = ffma2(hp.x, d1, acc[p][1]);
                acc[p][2]   = ffma2(hp.x, d2, acc[p][2]);
                acc[p][3]   = ffma2(hp.x, d3, acc[p][3]);
                acc[p+1][0] = ffma2(hp.y, d0, acc[p+1][0]);
                acc[p+1][1] = ffma2(hp.y, d1, acc[p+1][1]);
                acc[p+1][2] = ffma2(hp.y, d2, acc[p+1][2]);
                acc[p+1][3] = ffma2(hp.y, d3, acc[p+1][3]);
            }
        }
        #pragma unroll
        for (int p = 0; p < 8; p++) {
            ull t0 = fadd2(acc[p][0], nl[p]);
            ull t1 = fadd2(acc[p][1], nl[p]);
            ull t2 = fadd2(acc[p][2], nl[p]);
            ull t3 = fadd2(acc[p][3], nl[p]);
            float a0, b0, a1, b1, a2, b2, a3, b3;
            unpack2(t0, a0, b0); unpack2(t1, a1, b1);
            unpack2(t2, a2, b2); unpack2(t3, a3, b3);
            float4 r0v = make_float4(a0, a1, a2, a3);
            float4 r1v = make_float4(b0, b1, b2, b3);
            *reinterpret_cast<float4*>(out + (size_t)(row0 + 2 * p) * V_ + vg) = r0v;
            *reinterpret_cast<float4*>(out + (size_t)(row0 + 2 * p + 1) * V_ + vg) = r1v;
        }
    }
}

// ---------------- launch --------------------------------------------------
extern "C" void kernel_launch(void* const* d_in, const int* in_sizes, int n_in,
                              void* d_out, int out_size) {
    const int*   idx    = (const int*)  d_in[0];
    const float* lookup = (const float*)d_in[1];
    const float* wx     = (const float*)d_in[2];
    const float* wh     = (const float*)d_in[3];
    const float* wo     = (const float*)d_in[4];
    const float* h0     = (const float*)d_in[5];
    float* out = (float*)d_out;

    k_embed_xw<<<ROWS / 128, 128>>>(idx, lookup, wx);
    k_rnn<<<1, B_ * H_>>>(wh, h0);
    k_lse_partial<<<dim3(ROWS / 16, NCHUNK), 128>>>(wo);
    k_lse_final<<<ROWS / 256, 256>>>();
    k_out<<<dim3(ROWS / 16, NCHUNK), 128>>>(wo, out);
}

// round 8
// speedup vs baseline: 1.9468x; 1.9468x over previous
#include <cuda_runtime.h>
#include <cuda_bf16.h>
#include <cstdint>
#include <cstddef>

#define S_    128
#define B_    64
#define V_    32000
#define E_    32
#define H_    16
#define ROWS  8192
#define NWARP 8
#define WCOLS (V_ / NWARP)      // 4000 cols per warp
#define NGRP  (WCOLS / 8)       // 500 mma groups per warp

// ---------------- device scratch ----------------
__device__ float g_xw[ROWS * H_];
__device__ float g_h[ROWS * H_];
__device__ float g_part[NWARP * ROWS];
__device__ float g_lse[ROWS];

// ---------------- helpers ----------------
__device__ __forceinline__ uint32_t bf16x2_of(float lo, float hi) {
    uint32_t r;
    asm("cvt.rn.bf16x2.f32 %0, %1, %2;" : "=r"(r) : "f"(hi), "f"(lo));
    return r;
}
__device__ __forceinline__ void mma_bf16(float& c0, float& c1, float& c2, float& c3,
                                         const uint32_t a[4], uint32_t b0, uint32_t b1) {
    asm volatile(
        "mma.sync.aligned.m16n8k16.row.col.f32.bf16.bf16.f32 "
        "{%0,%1,%2,%3}, {%4,%5,%6,%7}, {%8,%9}, {%0,%1,%2,%3};"
        : "+f"(c0), "+f"(c1), "+f"(c2), "+f"(c3)
        : "r"(a[0]), "r"(a[1]), "r"(a[2]), "r"(a[3]), "r"(b0), "r"(b1));
}

// ---------------- k1: xw = lookup[idx] @ Wx ----------------
__global__ void k_embed_xw(const int* __restrict__ idx,
                           const float* __restrict__ lookup,
                           const float* __restrict__ wx) {
    __shared__ float sWx[E_ * H_];
    for (int i = threadIdx.x; i < E_ * H_; i += blockDim.x) sWx[i] = wx[i];
    __syncthreads();
    int r = blockIdx.x * blockDim.x + threadIdx.x;
    int id = idx[r];
    float x[E_];
    const float4* lp = reinterpret_cast<const float4*>(lookup + (size_t)id * E_);
    #pragma unroll
    for (int i = 0; i < E_ / 4; i++) {
        float4 t = lp[i];
        x[4*i] = t.x; x[4*i+1] = t.y; x[4*i+2] = t.z; x[4*i+3] = t.w;
    }
    #pragma unroll
    for (int h = 0; h < H_; h++) {
        float a = 0.f;
        #pragma unroll
        for (int e = 0; e < E_; e++) a += x[e] * sWx[e * H_ + h];
        g_xw[r * H_ + h] = a;
    }
}

// ---------------- k2: sequential recurrence ----------------
__global__ void k_rnn(const float* __restrict__ wh, const float* __restrict__ h0) {
    __shared__ float sWh[H_ * H_];
    __shared__ float sh[B_ * H_];
    int tid = threadIdx.x;                 // 1024 threads
    if (tid < H_ * H_) sWh[tid] = wh[tid];
    sh[tid] = h0[tid];
    __syncthreads();
    int b = tid >> 4, j = tid & 15;
    float pre = g_xw[tid];
    for (int s = 0; s < S_; s++) {
        float a = pre;
        float nxt = (s < S_ - 1) ? g_xw[(s + 1) * (B_ * H_) + tid] : 0.f;
        #pragma unroll
        for (int k = 0; k < H_; k++) a += sh[b * H_ + k] * sWh[k * H_ + j];
        float hn = tanhf(a);
        __syncthreads();
        sh[tid] = hn;
        g_h[s * (B_ * H_) + tid] = hn;
        pre = nxt;
        __syncthreads();
    }
}

// ---------------- projection via mma.sync bf16 ----------------
// PASS 0: per-warp expsum partials.  PASS 1: out = logits - lse.
// CTA: 256 thr / 8 warps, 32 rows (2 m-tiles). Warp w owns V-slice [w*4000, ..).
template <int PASS>
__global__ __launch_bounds__(256)
void k_proj(const float* __restrict__ wo, float* __restrict__ out) {
    int tid = threadIdx.x, lane = tid & 31, w = tid >> 5;
    int g = lane >> 2, c = lane & 3;
    int row0 = blockIdx.x * 32;

    // ---- A fragments: rows of h, resident for the whole kernel ----
    uint32_t A[2][4];
    #pragma unroll
    for (int mt = 0; mt < 2; mt++) {
        int r0 = row0 + mt * 16 + g;
        const float* h0 = g_h + (size_t)r0 * H_;
        const float* h8 = g_h + (size_t)(r0 + 8) * H_;
        float2 x0 = *reinterpret_cast<const float2*>(h0 + 2 * c);
        float2 x1 = *reinterpret_cast<const float2*>(h8 + 2 * c);
        float2 x2 = *reinterpret_cast<const float2*>(h0 + 2 * c + 8);
        float2 x3 = *reinterpret_cast<const float2*>(h8 + 2 * c + 8);
        A[mt][0] = bf16x2_of(x0.x, x0.y);
        A[mt][1] = bf16x2_of(x1.x, x1.y);
        A[mt][2] = bf16x2_of(x2.x, x2.y);
        A[mt][3] = bf16x2_of(x3.x, x3.y);
    }

    float nl[2][2];
    if (PASS == 1) {
        #pragma unroll
        for (int mt = 0; mt < 2; mt++) {
            nl[mt][0] = -g_lse[row0 + mt * 16 + g];
            nl[mt][1] = -g_lse[row0 + mt * 16 + g + 8];
        }
    }

    // B pointers: rows k = 2c, 2c+1, 2c+8, 2c+9 of Wo, col = w*4000 + g
    int vcol0 = w * WCOLS + g;
    const float* pa = wo + (size_t)(2 * c) * V_ + vcol0;
    const float* pb = pa + V_;
    const float* pc = pa + (size_t)8 * V_;
    const float* pd = pc + V_;

    float s00 = 0.f, s01 = 0.f, s10 = 0.f, s11 = 0.f;

    float f0 = pa[0], f1 = pb[0], f2 = pc[0], f3 = pd[0];

    #pragma unroll 2
    for (int grp = 0; grp < NGRP; grp++) {
        int nxt = (grp + 1 < NGRP) ? (grp + 1) * 8 : grp * 8;
        float n0 = pa[nxt], n1 = pb[nxt], n2 = pc[nxt], n3 = pd[nxt];

        uint32_t b0 = bf16x2_of(f0, f1);
        uint32_t b1 = bf16x2_of(f2, f3);

        #pragma unroll
        for (int mt = 0; mt < 2; mt++) {
            float c0 = 0.f, c1 = 0.f, c2 = 0.f, c3 = 0.f;
            mma_bf16(c0, c1, c2, c3, A[mt], b0, b1);
            if (PASS == 0) {
                if (mt == 0) {
                    s00 += __expf(c0) + __expf(c1);
                    s01 += __expf(c2) + __expf(c3);
                } else {
                    s10 += __expf(c0) + __expf(c1);
                    s11 += __expf(c2) + __expf(c3);
                }
            } else {
                int col = w * WCOLS + grp * 8 + 2 * c;
                float2 v0 = make_float2(c0 + nl[mt][0], c1 + nl[mt][0]);
                float2 v1 = make_float2(c2 + nl[mt][1], c3 + nl[mt][1]);
                *reinterpret_cast<float2*>(
                    out + (size_t)(row0 + mt * 16 + g) * V_ + col) = v0;
                *reinterpret_cast<float2*>(
                    out + (size_t)(row0 + mt * 16 + g + 8) * V_ + col) = v1;
            }
        }
        f0 = n0; f1 = n1; f2 = n2; f3 = n3;
    }

    if (PASS == 0) {
        // reduce over the 4 lanes sharing a row (lane&3 = 0..3)
        #pragma unroll
        for (int off = 1; off <= 2; off <<= 1) {
            s00 += __shfl_xor_sync(0xffffffffu, s00, off);
            s01 += __shfl_xor_sync(0xffffffffu, s01, off);
            s10 += __shfl_xor_sync(0xffffffffu, s10, off);
            s11 += __shfl_xor_sync(0xffffffffu, s11, off);
        }
        if (c == 0) {
            float* gp = g_part + (size_t)w * ROWS;
            gp[row0 + g]          = s00;
            gp[row0 + g + 8]      = s01;
            gp[row0 + 16 + g]     = s10;
            gp[row0 + 16 + g + 8] = s11;
        }
    }
}

// ---------------- k4: lse = log(sum of partials) ----------------------
__global__ void k_lse_final() {
    int r = blockIdx.x * blockDim.x + threadIdx.x;
    float s = 0.f;
    #pragma unroll
    for (int c = 0; c < NWARP; c++) s += g_part[(size_t)c * ROWS + r];
    g_lse[r] = logf(s);
}

// ---------------- launch --------------------------------------------------
extern "C" void kernel_launch(void* const* d_in, const int* in_sizes, int n_in,
                              void* d_out, int out_size) {
    const int*   idx    = (const int*)  d_in[0];
    const float* lookup = (const float*)d_in[1];
    const float* wx     = (const float*)d_in[2];
    const float* wh     = (const float*)d_in[3];
    const float* wo     = (const float*)d_in[4];
    const float* h0     = (const float*)d_in[5];
    float* out = (float*)d_out;

    k_embed_xw<<<ROWS / 128, 128>>>(idx, lookup, wx);
    k_rnn<<<1, B_ * H_>>>(wh, h0);
    k_proj<0><<<ROWS / 32, 256>>>(wo, nullptr);
    k_lse_final<<<ROWS / 256, 256>>>();
    k_proj<1><<<ROWS / 32, 256>>>(wo, out);
}